// round 16
// baseline (speedup 1.0000x reference)
#include <cuda_runtime.h>

// Kannala-Brandt fisheye round-trip — converged memory-floor kernel.
//
// The task streams 67MB of mandated fp32 traffic; measured 10.7us across four
// distinct structures (R12-R15) = the memory-path streaming floor. Compute is
// slack (issue ~56%), so the math uses the higher-accuracy validated form:
//
//   ru = |(px-cx)/fx, (py-cy)/fy|      (sqrt via MUFU.RSQ: ru = q*rsqrt(q))
//   t:  2 fixed-point steps of t <- t - (t*d(t) - ru)
//   out = sinc(t)*(pixel-center) + center   (deg-8 Taylor sinc;
//        d(t)*sin(t)/ru == sin(t)/t at the fixed point, focal lengths cancel)
//   rel_err 6.2e-6 vs 1e-3 tolerance.
//
// R16 micro-lever: streaming cache hints — input lines are single-use per
// launch (ld.global.nc.cs), output is produce-only (st.global.cs) — letting
// LTS retire lines without re-reference bookkeeping at the throughput cap.

#define CX 640.0f
#define CY 480.0f

#define XTHREADS 256

struct KParams { float k0, k1, k2, k3, k4, rfx, rfy; };

__device__ __forceinline__ float4 ldg_cs(const float4* p) {
    float4 v;
    asm volatile("ld.global.nc.cs.v4.f32 {%0,%1,%2,%3}, [%4];"
                 : "=f"(v.x), "=f"(v.y), "=f"(v.z), "=f"(v.w) : "l"(p));
    return v;
}
__device__ __forceinline__ void stg_cs(float4* p, float4 v) {
    asm volatile("st.global.cs.v4.f32 [%0], {%1,%2,%3,%4};"
                 :: "l"(p), "f"(v.x), "f"(v.y), "f"(v.z), "f"(v.w) : "memory");
}

__device__ __forceinline__ KParams load_params(const float* kvec,
                                               const float* fx_p,
                                               const float* fy_p)
{
    KParams P;
    P.k0 = __ldg(&kvec[0]); P.k1 = __ldg(&kvec[1]); P.k2 = __ldg(&kvec[2]);
    P.k3 = __ldg(&kvec[3]); P.k4 = __ldg(&kvec[4]);
    P.rfx = __fdividef(1.0f, __ldg(fx_p));
    P.rfy = __fdividef(1.0f, __ldg(fy_p));
    return P;
}

__device__ __forceinline__ float2 kb_point(float px, float py, const KParams& P)
{
    float dx = px - CX;
    float dy = py - CY;
    float mx = dx * P.rfx;
    float my = dy * P.rfy;
    float q  = fmaf(mx, mx, fmaf(my, my, 1e-30f));
    float ru = q * rsqrtf(q);                       // sqrt(q)

    // 2 fixed-point steps on t*d(t) = ru
    float t = ru;
#pragma unroll
    for (int it = 0; it < 2; ++it) {
        float p = ((((P.k4 * t + P.k3) * t + P.k2) * t + P.k1) * t + P.k0);
        float r = fmaf(p, t, -ru);
        t = t - r;
    }

    // w = sinc(t), deg-8 Taylor in t^2
    float t2 = t * t;
    float w = fmaf(t2, fmaf(t2, fmaf(t2, fmaf(t2, 2.7557319e-6f, -1.9841270e-4f),
                                     8.3333333e-3f), -1.6666667e-1f), 1.0f);

    return make_float2(fmaf(w, dx, CX), fmaf(w, dy, CY));
}

// ---- specialized: n_pairs == gridDim.x * XTHREADS * ITERS exactly ----
template <int ITERS>
__global__ void __launch_bounds__(XTHREADS)
kb_exact_kernel(const float4* __restrict__ in4,
                const float*  __restrict__ kvec,
                const float*  __restrict__ fx_p,
                const float*  __restrict__ fy_p,
                float4*       __restrict__ out4)
{
    const int stride = gridDim.x * XTHREADS;
    const int base   = blockIdx.x * XTHREADS + threadIdx.x;
    const KParams P  = load_params(kvec, fx_p, fy_p);

    float4 v[ITERS];
#pragma unroll
    for (int k = 0; k < ITERS; ++k)
        v[k] = ldg_cs(&in4[base + k * stride]);     // independent LDG.128

#pragma unroll
    for (int k = 0; k < ITERS; ++k) {
        float2 a = kb_point(v[k].x, v[k].y, P);
        float2 b = kb_point(v[k].z, v[k].w, P);
        stg_cs(&out4[base + k * stride], make_float4(a.x, a.y, b.x, b.y));
    }
}

// ---- generic fallback ----
__global__ void __launch_bounds__(256)
kb_generic_kernel(const float4* __restrict__ in4,
                  const float2* __restrict__ in2,
                  const float*  __restrict__ kvec,
                  const float*  __restrict__ fx_p,
                  const float*  __restrict__ fy_p,
                  float4*       __restrict__ out4,
                  float2*       __restrict__ out2,
                  int n_pairs, int n_tail_pts)
{
    const int stride = gridDim.x * blockDim.x;
    int i = blockIdx.x * blockDim.x + threadIdx.x;
    const KParams P = load_params(kvec, fx_p, fy_p);

    for (; i < n_pairs; i += stride) {
        float4 p = in4[i];
        float2 a = kb_point(p.x, p.y, P);
        float2 b = kb_point(p.z, p.w, P);
        out4[i] = make_float4(a.x, a.y, b.x, b.y);
    }

    if (n_tail_pts && blockIdx.x == 0 && threadIdx.x == 0) {
        for (int j = 0; j < n_tail_pts; ++j) {
            int idx = 2 * n_pairs + j;
            float2 p = in2[idx];
            out2[idx] = kb_point(p.x, p.y, P);
        }
    }
}

extern "C" void kernel_launch(void* const* d_in, const int* in_sizes, int n_in,
                              void* d_out, int out_size)
{
    const float* uv = (const float*)d_in[0];   // [N,2] fp32
    const float* kv = (const float*)d_in[1];   // k_vector [5]
    const float* fx = (const float*)d_in[2];
    const float* fy = (const float*)d_in[3];

    int n       = in_sizes[0] / 2;
    int n_pairs = n / 2;
    int n_tail  = n - 2 * n_pairs;

    const int ITERS = 2;
    if (n_tail == 0 && n_pairs % (XTHREADS * ITERS) == 0) {
        // bench shape: N = 4194304 -> n_pairs = 2^21 = 4096 * 256 * 2
        int blocks = n_pairs / (XTHREADS * ITERS);
        kb_exact_kernel<ITERS><<<blocks, XTHREADS>>>(
            (const float4*)uv, kv, fx, fy, (float4*)d_out);
    } else {
        const int threads = 256;
        int blocks = 148 * 8;
        int need   = (n_pairs + threads - 1) / threads;
        if (need < blocks) blocks = need > 0 ? need : 1;
        kb_generic_kernel<<<blocks, threads>>>(
            (const float4*)uv, (const float2*)uv, kv, fx, fy,
            (float4*)d_out, (float2*)d_out, n_pairs, n_tail);
    }
}